// round 15
// baseline (speedup 1.0000x reference)
#include <cuda_runtime.h>
#include <cstdint>

// Problem constants
#define DD   4096
#define OBJN 20
#define MCNT 1000
#define FR   20
#define BB   4
#define QQ   4
#define NROWS 32        // compacted rows: 16 high + 16 low
#define NF4  480        // MPB=4 fused units (m 0..959 per sel)
#define NF1  80         // MPB=1 fused units (m 960..999 per sel)
#define NFT  560        // total fused
#define NCOPY 1600      // consolidated copy tiles (bf, o)
#define REGA 2240       // fused/copy interleave region (every 4th fused)
#define NSPEC 640       // deferred hi/lo mem-sourced writes
#define GRIDN (REGA + NSPEC)

#define RP_ELEMS 26214400ull          // Q*B*F*OBJ*D
#define OUT_HIGH (2ull*RP_ELEMS)      // 52428800
#define OUT_LOW  (2ull*RP_ELEMS + 16ull)

typedef unsigned long long ull;

// ---------------- scratch (device globals; no allocation allowed) ----------
__device__ int   g_high[16];
__device__ int   g_low[16];
__device__ int   g_rowbf[32];                 // compact row -> b*20+f
__device__ float g_invn[BB*FR*OBJN];          // per-region inverse norms
__device__ float g_Rmax[BB*FR*DD];            // UNNORMALIZED max-pooled rows
__device__ ull   g_best[64];                  // [sel*32+row] encoded (score,idx)
__device__ int   g_sim_unused[1];
__device__ int   g_ctr;                       // fused-done counter
__device__ int   g_flag;                      // sims-published flag

// ---------------- helpers ---------------------------------------------------
__device__ __forceinline__ float blockReduceSum256(float v, float* sh) {
    #pragma unroll
    for (int o = 16; o > 0; o >>= 1) v += __shfl_xor_sync(0xffffffffu, v, o);
    int lane = threadIdx.x & 31, w = threadIdx.x >> 5;
    if (lane == 0) sh[w] = v;
    __syncthreads();
    if (threadIdx.x < 32) {
        float r = (threadIdx.x < 8) ? sh[threadIdx.x] : 0.f;
        #pragma unroll
        for (int o = 4; o > 0; o >>= 1) r += __shfl_xor_sync(0xffffffffu, r, o);
        if (threadIdx.x == 0) sh[0] = r;
    }
    __syncthreads();
    float res = sh[0];
    __syncthreads();
    return res;
}

__device__ __forceinline__ void ffma2(ull& d, ull a, ull b) {
    asm("fma.rn.f32x2 %0, %1, %2, %0;" : "+l"(d) : "l"(a), "l"(b));
}
__device__ __forceinline__ ull packf2(float x, float y) {
    ull r; asm("mov.b64 %0, {%1,%2};" : "=l"(r) : "f"(x), "f"(y)); return r;
}
__device__ __forceinline__ float unpack_add(ull a) {
    unsigned lo, hi;
    asm("mov.b64 {%0,%1}, %2;" : "=r"(lo), "=r"(hi) : "l"(a));
    return __uint_as_float(lo) + __uint_as_float(hi);
}

// ---------------- K1: per-region inverse norms + idx side-work + resets -----
__global__ void __launch_bounds__(256) k_norms(const float* __restrict__ qr,
                                               const int* __restrict__ rnd,
                                               const float* __restrict__ inp) {
    int row = blockIdx.x;            // 0..1599 == bf*20 + o
    int t   = threadIdx.x;

    if (row == 0) {                  // resets for graph replays
        if (t == 0) { g_ctr = 0; g_flag = 0; }
        if (t >= 64 && t < 128) g_best[t - 64] = 0ull;
    }
    if (row == 0 && t >= 32 && t < 48) {     // warp 1: top-k / rank select
        int tt = t - 32;
        int b = tt >> 2;
        const float* v = qr + tt * FR;
        int hi = 0; float hv = v[0];
        for (int i = 1; i < FR; i++) { float x = v[i]; if (x > hv) { hv = x; hi = i; } }
        int r = rnd[tt];
        int lo = 0;
        for (int i = 0; i < FR; i++) {
            int rank = 0;
            float c = v[i];
            for (int j = 0; j < FR; j++) {
                float a = v[j];
                rank += (a < c) || (a == c && j < i);
            }
            if (rank == r) { lo = i; break; }
        }
        g_high[tt] = hi;
        g_low[tt]  = lo;
        g_rowbf[tt]      = b * FR + hi;
        g_rowbf[16 + tt] = b * FR + lo;
    }

    __shared__ float sh[32];
    const float4* p = (const float4*)(inp + (size_t)row * DD);
    float s = 0.f;
    #pragma unroll
    for (int i = 0; i < 4; i++) {
        float4 v = __ldg(p + t + i * 256);
        s += v.x*v.x + v.y*v.y + v.z*v.z + v.w*v.w;
    }
    float tot = blockReduceSum256(s, sh);
    if (t == 0) g_invn[row] = 1.0f / fmaxf(sqrtf(tot), 1e-12f);
}

// ---------------- K2: scaled max-pool (column-sliced, input L2-hot) ---------
__global__ void __launch_bounds__(256) k_pool(const float* __restrict__ inp) {
    int bf = blockIdx.x;             // 0..79
    int c  = blockIdx.y * 256 + threadIdx.x;   // f4 col 0..1023
    __shared__ float s_inv[OBJN];
    if (threadIdx.x < OBJN) s_inv[threadIdx.x] = g_invn[bf * OBJN + threadIdx.x];
    __syncthreads();

    const float4* base = (const float4*)(inp + (size_t)bf * (OBJN * DD));
    float4 mx = make_float4(-3.4e38f, -3.4e38f, -3.4e38f, -3.4e38f);
    #pragma unroll 4
    for (int o = 0; o < OBJN; o++) {
        float inv = s_inv[o];
        float4 v = __ldg(base + o * (DD / 4) + c);
        mx.x = fmaxf(mx.x, v.x * inv);
        mx.y = fmaxf(mx.y, v.y * inv);
        mx.z = fmaxf(mx.z, v.z * inv);
        mx.w = fmaxf(mx.w, v.w * inv);
    }
    ((float4*)(g_Rmax + (size_t)bf * DD))[c] = mx;
}

// ---------------- fused unit: stream NM mem rows, pool, dot, atomicMax ------
template<int NM>
__device__ __forceinline__ void fused_unit(int sel, int m0,
        const float* __restrict__ mem, int t,
        float* sh, float* s_inv, int* rb, float (*s_red)[8][4]) {
    int lane = t & 31, w = t >> 5;
    int rstart = sel ? 0 : 16;           // sel0 only needs low rows
    if (t < NROWS) rb[t] = g_rowbf[t] * (DD / 4);

    float4 pm[NM][4];
    #pragma unroll
    for (int mi = 0; mi < NM; mi++) {
        #pragma unroll
        for (int i = 0; i < 4; i++)
            pm[mi][i] = make_float4(-3.4e38f, -3.4e38f, -3.4e38f, -3.4e38f);
        const float4* base = (const float4*)(mem + (size_t)(m0 + mi) * (OBJN * DD));
        for (int o = 0; o < OBJN; o++) {
            const float4* p = base + o * (DD / 4);
            #pragma unroll
            for (int i = 0; i < 4; i++) {
                float4 v = __ldcs(p + t + i * 256);
                pm[mi][i].x = fmaxf(pm[mi][i].x, v.x);
                pm[mi][i].y = fmaxf(pm[mi][i].y, v.y);
                pm[mi][i].z = fmaxf(pm[mi][i].z, v.z);
                pm[mi][i].w = fmaxf(pm[mi][i].w, v.w);
            }
        }
        float s = 0.f;
        #pragma unroll
        for (int i = 0; i < 4; i++)
            s += pm[mi][i].x*pm[mi][i].x + pm[mi][i].y*pm[mi][i].y
               + pm[mi][i].z*pm[mi][i].z + pm[mi][i].w*pm[mi][i].w;
        float tot = blockReduceSum256(s, sh);    // syncthreads covers rb too
        if (t == 0) s_inv[mi] = 1.0f / fmaxf(sqrtf(tot), 1e-12f);
    }

    ull pp[NM][8];
    #pragma unroll
    for (int mi = 0; mi < NM; mi++)
        #pragma unroll
        for (int i = 0; i < 4; i++) {
            pp[mi][2*i]   = packf2(pm[mi][i].x, pm[mi][i].y);
            pp[mi][2*i+1] = packf2(pm[mi][i].z, pm[mi][i].w);
        }

    for (int r = rstart; r < NROWS; r++) {
        const float4* R4 = ((const float4*)g_Rmax) + rb[r] + t;
        ull acc[NM];
        #pragma unroll
        for (int mi = 0; mi < NM; mi++) acc[mi] = 0ull;
        #pragma unroll
        for (int i = 0; i < 4; i++) {
            float4 rv = __ldg(R4 + i * 256);
            ull r0 = packf2(rv.x, rv.y), r1 = packf2(rv.z, rv.w);
            #pragma unroll
            for (int mi = 0; mi < NM; mi++) {
                ffma2(acc[mi], pp[mi][2*i],   r0);
                ffma2(acc[mi], pp[mi][2*i+1], r1);
            }
        }
        float p[NM];
        #pragma unroll
        for (int mi = 0; mi < NM; mi++) p[mi] = unpack_add(acc[mi]);
        #pragma unroll
        for (int o = 16; o > 0; o >>= 1)
            #pragma unroll
            for (int mi = 0; mi < NM; mi++)
                p[mi] += __shfl_xor_sync(0xffffffffu, p[mi], o);
        if (lane == 0)
            #pragma unroll
            for (int mi = 0; mi < NM; mi++) s_red[r][w][mi] = p[mi];
    }
    __syncthreads();
    if (t < NROWS * NM) {
        int r = t / NM, mi = t % NM;
        if (r >= rstart) {
            float s = 0.f;
            #pragma unroll
            for (int ww = 0; ww < 8; ww++) s += s_red[r][ww][mi];
            s *= s_inv[mi];
            unsigned u = __float_as_uint(s);
            u ^= (u >> 31) ? 0xFFFFFFFFu : 0x80000000u;
            ull pv = ((ull)u << 32) | (unsigned)(0xFFFFFFFFu - (unsigned)(m0 + mi));
            atomicMax(&g_best[sel * 32 + r], pv);
        }
    }
}

// ---------------- K3: MIXED kernel: fused + consolidated copies + spec ------
__global__ void __launch_bounds__(256) k_main(const float* __restrict__ mem1,
                                              const float* __restrict__ mem2,
                                              const float* __restrict__ inp,
                                              float* __restrict__ out) {
    int bx = blockIdx.x;
    int t  = threadIdx.x;

    __shared__ float sh[32];
    __shared__ float s_inv[4];
    __shared__ int   rb[NROWS];
    __shared__ float s_red[NROWS][8][4];
    __shared__ int   s_last;
    __shared__ unsigned s_sm;

    if (bx < REGA && (bx & 3) == 0) {
        // ----- fused memory-bank streamer -----
        int f_id = bx >> 2;                  // 0..559
        if (f_id < NF4) {
            int sel = f_id & 1, m0 = (f_id >> 1) * 4;
            fused_unit<4>(sel, m0, sel ? mem2 : mem1, t, sh, s_inv, rb, s_red);
        } else {
            int u = f_id - NF4;              // 0..79 (short tail blocks)
            int sel = u & 1, m0 = 960 + (u >> 1);
            fused_unit<1>(sel, m0, sel ? mem2 : mem1, t, sh, s_inv, rb, s_red);
        }
        __syncthreads();
        if (t == 0) {
            __threadfence();
            s_last = (atomicAdd(&g_ctr, 1) == NFT - 1) ? 1 : 0;
        }
        __syncthreads();
        if (s_last) {
            if (t < 16) {                    // publish sim scalar outputs
                int bq = t, b = bq >> 2, q = bq & 3;
                unsigned s2 = (unsigned)(g_best[32 + bq] & 0xFFFFFFFFu);
                out[OUT_HIGH + q * 4 + b] = (float)(0xFFFFFFFFu - s2);
                unsigned s1 = (unsigned)(g_best[16 + bq] & 0xFFFFFFFFu);
                out[OUT_LOW + q * 4 + b] = (float)(0xFFFFFFFFu - s1);
            }
            __syncthreads();
            if (t == 0) { __threadfence(); atomicExch(&g_flag, 1); }
        }
    } else if (bx < REGA) {
        // ----- consolidated copy tile: one (bf, o) -> all 4 q positions -----
        int copy_id = bx - (bx >> 2) - 1;    // 0..1679
        if (copy_id >= NCOPY) return;
        int bf = copy_id / OBJN, o = copy_id - bf * OBJN;
        int b  = bf / FR, f = bf - b * FR;
        const float4* pr = (const float4*)(inp + ((size_t)bf * OBJN + o) * DD);
        float invn = g_invn[bf * OBJN + o];
        float4 v[4];
        #pragma unroll
        for (int i = 0; i < 4; i++) {
            v[i] = __ldg(pr + t + i * 256);
            v[i].x *= invn; v[i].y *= invn; v[i].z *= invn; v[i].w *= invn;
        }
        #pragma unroll
        for (int q = 0; q < QQ; q++) {
            int bq = b * QQ + q;
            int hi = g_high[bq], lo = g_low[bq];
            size_t outoff = (((size_t)(q * 80 + bf)) * OBJN + o) * DD;
            float4* op = (float4*)(out + outoff);
            float4* on = (float4*)(out + RP_ELEMS + outoff);
            if (f != lo) {                   // Rp = R (deferred when f==lo)
                #pragma unroll
                for (int i = 0; i < 4; i++) __stcs(op + t + i * 256, v[i]);
            }
            if (f != hi) {                   // Rn = R (deferred when f==hi)
                #pragma unroll
                for (int i = 0; i < 4; i++) __stcs(on + t + i * 256, v[i]);
            }
        }
    } else {
        // ----- deferred mem-sourced writes (spin until sims published) -----
        int sid = bx - REGA;                 // 0..639
        int o = sid % OBJN, s = sid / OBJN;  // s: 0..31
        int bq = s & 15, kind = s >> 4;      // kind0: f=hi (Rn<-mem2); kind1: f=lo (Rp<-mem1)
        int b = bq >> 2, q = bq & 3;
        int f = kind ? g_low[bq] : g_high[bq];
        if (t == 0) {
            while (atomicAdd(&g_flag, 0) == 0) __nanosleep(200);
            __threadfence();
            int row = kind ? (16 + bq) : (48 + bq);   // sim1@low : sim2@low
            s_sm = 0xFFFFFFFFu - (unsigned)(g_best[row] & 0xFFFFFFFFu);
        }
        __syncthreads();
        unsigned sm = s_sm;
        size_t outoff = (((size_t)(q * 80 + b * FR + f)) * OBJN + o) * DD;
        if (kind == 0) {
            const float4* pmem = (const float4*)(mem2 + (size_t)sm * (OBJN * DD) + (size_t)o * DD);
            float4* on = (float4*)(out + RP_ELEMS + outoff);
            #pragma unroll
            for (int i = 0; i < 4; i++) __stcs(on + t + i * 256, __ldg(pmem + t + i * 256));
        } else {
            const float4* pmem = (const float4*)(mem1 + (size_t)sm * (OBJN * DD) + (size_t)o * DD);
            float4* op = (float4*)(out + outoff);
            #pragma unroll
            for (int i = 0; i < 4; i++) __stcs(op + t + i * 256, __ldg(pmem + t + i * 256));
        }
    }
}

// ---------------- launch -----------------------------------------------------
extern "C" void kernel_launch(void* const* d_in, const int* in_sizes, int n_in,
                              void* d_out, int out_size) {
    const float* qr   = (const float*)d_in[0];   // [4,4,20]
    const float* inp  = (const float*)d_in[1];   // [4,20,20,4096]
    const float* mem1 = (const float*)d_in[2];   // [1000,81920]
    const float* mem2 = (const float*)d_in[3];   // [1000,81920]
    const int*   rnd  = (const int*)d_in[4];     // [4,4,1]
    float* out = (float*)d_out;

    k_norms<<<1600, 256>>>(qr, rnd, inp);
    k_pool<<<dim3(80, 4), 256>>>(inp);
    k_main<<<GRIDN, 256>>>(mem1, mem2, inp, out);
}